// round 16
// baseline (speedup 1.0000x reference)
#include <cuda_runtime.h>
#include <cuda_fp16.h>
#include <cstdint>

#define T_TOKENS 4096
#define DIM      2048
#define NEXP     8
#define HDIM     1024
#define HSDIM    2048
#define NSLOTS   8192
#define PAD      128

// ---------------- scratch (device globals; no allocation allowed) ----------------
__device__ __half g_xr[(size_t)T_TOKENS * DIM];          // fp16 dense x
__device__ __half g_hbuf[(size_t)(NSLOTS + PAD) * HDIM]; // routed h (weight-folded)
__device__ __half g_sh[(size_t)T_TOKENS * HSDIM];        // shared-expert h
__device__ __half g_wgh[(size_t)NEXP * DIM * HDIM];      // transposed [e][n=h][k=d] fp16
__device__ __half g_wuh[(size_t)NEXP * DIM * HDIM];
__device__ __half g_wdh[(size_t)NEXP * HDIM * DIM];      // [e][n=d][k=h]
__device__ __half g_swgh[(size_t)DIM * HSDIM];           // [n=hs][k=d]
__device__ __half g_swuh[(size_t)DIM * HSDIM];
__device__ __half g_swdh[(size_t)HSDIM * DIM];           // [n=d][k=hs]
__device__ int   g_slot_token[NSLOTS];
__device__ float g_slot_w[NSLOTS];
__device__ int   g_counts[NEXP];
__device__ int   g_fill[NEXP];
__device__ int   g_offsets[NEXP + 1];
__device__ int   g_eidx[NSLOTS];
__device__ float g_topw[NSLOTS];

// ---------------- helpers ----------------
__device__ __forceinline__ float silu_f(float g) {
    return g * (1.0f / (1.0f + __expf(-g)));
}
__device__ __forceinline__ uint32_t s2u(const void* p) {
    uint32_t a;
    asm("{ .reg .u64 t; cvta.to.shared.u64 t, %1; cvt.u32.u64 %0, t; }" : "=r"(a) : "l"(p));
    return a;
}
__device__ __forceinline__ void cp16(uint32_t s, const void* g) {
    asm volatile("cp.async.cg.shared.global [%0], [%1], 16;" :: "r"(s), "l"(g));
}
__device__ __forceinline__ void cp_commit() {
    asm volatile("cp.async.commit_group;" ::: "memory");
}
__device__ __forceinline__ void mma16(float* c, const uint32_t* a, const uint32_t* b) {
    asm volatile("mma.sync.aligned.m16n8k16.row.col.f32.f16.f16.f32 "
        "{%0,%1,%2,%3}, {%4,%5,%6,%7}, {%8,%9}, {%0,%1,%2,%3};"
        : "+f"(c[0]), "+f"(c[1]), "+f"(c[2]), "+f"(c[3])
        : "r"(a[0]), "r"(a[1]), "r"(a[2]), "r"(a[3]), "r"(b[0]), "r"(b[1]));
}
__device__ __forceinline__ void ldsm4(uint32_t* d, uint32_t addr) {
    asm volatile("ldmatrix.sync.aligned.m8n8.x4.shared.b16 {%0,%1,%2,%3}, [%4];"
        : "=r"(d[0]), "=r"(d[1]), "=r"(d[2]), "=r"(d[3]) : "r"(addr));
}

// SMEM geometry: every tile (A or B) = 128 rows x 40 halves (32 data + 8 pad)
#define AST 40
#define TILE_B 10240                       // bytes per tile
#define GU_SMEM (3 * 3 * TILE_B)           // 92160 (3 stages x {A,Bg,Bu})
#define DN_SMEM (3 * 2 * TILE_B)           // 61440 (3 stages x {A,B})

// ---------------- routing kernels ----------------
__global__ void zero_small_kernel() {
    int i = threadIdx.x;
    if (i < NEXP) { g_counts[i] = 0; g_fill[i] = 0; }
}

__global__ void zero_out_kernel(float* __restrict__ out) {
    int i = blockIdx.x * blockDim.x + threadIdx.x;
    float4 z = make_float4(0.f, 0.f, 0.f, 0.f);
    ((float4*)out)[i] = z;
}

__global__ void join_kernel() {}

__global__ void router_kernel(const float* __restrict__ x, const float* __restrict__ rw) {
    int t = (blockIdx.x * blockDim.x + threadIdx.x) >> 5;
    int lane = threadIdx.x & 31;
    if (t >= T_TOKENS) return;
    const float* xr = x + (size_t)t * DIM;
    float lg[NEXP];
#pragma unroll
    for (int e = 0; e < NEXP; e++) lg[e] = 0.f;
    for (int d = lane; d < DIM; d += 32) {
        float xv = xr[d];
        const float* r = rw + (size_t)d * NEXP;
#pragma unroll
        for (int e = 0; e < NEXP; e++) lg[e] += xv * r[e];
    }
#pragma unroll
    for (int e = 0; e < NEXP; e++) {
#pragma unroll
        for (int o = 16; o; o >>= 1) lg[e] += __shfl_xor_sync(0xffffffffu, lg[e], o);
    }
    if (lane == 0) {
        float mx = lg[0];
#pragma unroll
        for (int e = 1; e < NEXP; e++) mx = fmaxf(mx, lg[e]);
        float p[NEXP];
#pragma unroll
        for (int e = 0; e < NEXP; e++) p[e] = __expf(lg[e] - mx);
        int i1 = 0;
#pragma unroll
        for (int e = 1; e < NEXP; e++) if (p[e] > p[i1]) i1 = e;
        int i2 = (i1 == 0) ? 1 : 0;
#pragma unroll
        for (int e = 0; e < NEXP; e++) if (e != i1 && p[e] > p[i2]) i2 = e;
        float w1 = p[i1], w2 = p[i2];
        float s = w1 + w2;
        w1 /= s; w2 /= s;
        g_eidx[2 * t] = i1; g_eidx[2 * t + 1] = i2;
        g_topw[2 * t] = w1; g_topw[2 * t + 1] = w2;
        atomicAdd(&g_counts[i1], 1);
        atomicAdd(&g_counts[i2], 1);
    }
}

__global__ void scan_kernel() {
    if (threadIdx.x == 0) {
        int acc = 0;
        for (int e = 0; e < NEXP; e++) { g_offsets[e] = acc; acc += g_counts[e]; }
        g_offsets[NEXP] = acc;
    }
}

__global__ void scatter_kernel() {
    int i = blockIdx.x * blockDim.x + threadIdx.x;
    if (i >= NSLOTS) return;
    int e = g_eidx[i];
    int pos = g_offsets[e] + atomicAdd(&g_fill[e], 1);
    g_slot_token[pos] = i >> 1;
    g_slot_w[pos] = g_topw[i];
}

// ---------------- weight fp32 [K][N] -> fp16 transposed [N][K] ----------------
__global__ void convw_t_kernel(const float* __restrict__ src, __half* __restrict__ dst,
                               int K, int N) {
    __shared__ float t[32][33];
    size_t boff = (size_t)blockIdx.z * K * N;
    const float* ip = src + boff;
    __half* op = dst + boff;
    int c0 = blockIdx.x * 32;  // N dim
    int r0 = blockIdx.y * 32;  // K dim
    int x = threadIdx.x, y = threadIdx.y;
#pragma unroll
    for (int i = 0; i < 32; i += 8)
        t[y + i][x] = ip[(size_t)(r0 + y + i) * N + (c0 + x)];
    __syncthreads();
    int tid = y * 32 + x;
#pragma unroll
    for (int q = 0; q < 2; q++) {
        int p = tid * 2 + q;
        int nl = p >> 4, kc = p & 15;
        __half2 h2 = __floats2half2_rn(t[2 * kc][nl], t[2 * kc + 1][nl]);
        *(__half2*)(op + (size_t)(c0 + nl) * K + r0 + 2 * kc) = h2;
    }
}

// dense fp32 -> fp16 activation conversion
__global__ void conv_x_kernel(const float* __restrict__ x) {
    int r = blockIdx.x;
    int c0 = threadIdx.x * 8;
    const float* src = x + (size_t)r * DIM;
    float4 v0 = *(const float4*)(src + c0);
    float4 v1 = *(const float4*)(src + c0 + 4);
    __half h[8];
    h[0] = __float2half(v0.x); h[1] = __float2half(v0.y);
    h[2] = __float2half(v0.z); h[3] = __float2half(v0.w);
    h[4] = __float2half(v1.x); h[5] = __float2half(v1.y);
    h[6] = __float2half(v1.z); h[7] = __float2half(v1.w);
    *(uint4*)(g_xr + (size_t)r * DIM + c0) = *(uint4*)h;
}

// ---------------- fused gate/up GEMM: mma.sync fp16 + ldmatrix, 3-stage ----------------
// Block 128x128, BK=32, 512 threads (16 warps 4x4), warp tile 32x32.
// ROUTED: A rows gathered inline from g_xr via g_slot_token.
template <bool ROUTED>
__global__ __launch_bounds__(512, 1)
void gateup_mma(const __half* __restrict__ Wg, const __half* __restrict__ Wu) {
    extern __shared__ char smem[];
    constexpr int KT = DIM / 32;  // 64
    uint32_t smA = s2u(smem);

    int tid = threadIdx.x, wid = tid >> 5, lane = tid & 31;
    int warpM = (wid >> 2) * 32, warpN = (wid & 3) * 32;
    int gl = lane >> 2, kl = lane & 3;
    int ntile = blockIdx.x, mtile = blockIdx.y;

    int start = 0, Me = T_TOKENS;
    if (ROUTED) {
        int expert = blockIdx.z;
        start = g_offsets[expert];
        Me = g_offsets[expert + 1] - start;
        if (mtile * 128 >= Me) return;
        Wg += (size_t)expert * DIM * HDIM;
        Wu += (size_t)expert * DIM * HDIM;
    }

    // cp.async lanes: row = tid/4 (0..127), seg = tid%4 (16B each)
    int crow = tid >> 2, seg = tid & 3;
    const __half* pA;
    if (ROUTED) {
        int rr = mtile * 128 + crow;
        if (rr >= Me) rr = Me - 1;                     // clamp; epilogue masks
        pA = g_xr + (size_t)g_slot_token[start + rr] * DIM + seg * 8;
    } else {
        pA = g_xr + (size_t)(mtile * 128 + crow) * DIM + seg * 8;
    }
    const __half* pG = Wg + (size_t)(ntile * 128 + crow) * DIM + seg * 8;
    const __half* pU = Wu + (size_t)(ntile * 128 + crow) * DIM + seg * 8;
    uint32_t dOff = smA + (crow * AST + seg * 8) * 2;

#define GU_COPY(stg, kt) do { \
    uint32_t _b = dOff + (stg) * (3 * TILE_B); \
    cp16(_b,              pA + (kt) * 32); \
    cp16(_b + TILE_B,     pG + (kt) * 32); \
    cp16(_b + 2 * TILE_B, pU + (kt) * 32); \
    cp_commit(); \
} while (0)

    // ldmatrix lane offsets (bytes within a tile)
    int l8 = lane & 7, lj = lane >> 3;
    uint32_t offA = (uint32_t)((warpM + (lj & 1) * 8 + l8) * AST + (lj >> 1) * 8) * 2;
    uint32_t offB = (uint32_t)((warpN + (lj >> 1) * 8 + l8) * AST + (lj & 1) * 8) * 2;

    float ag[2][4][4], au[2][4][4];
#pragma unroll
    for (int mm = 0; mm < 2; mm++)
#pragma unroll
        for (int nn = 0; nn < 4; nn++)
#pragma unroll
            for (int q = 0; q < 4; q++) { ag[mm][nn][q] = 0.f; au[mm][nn][q] = 0.f; }

    GU_COPY(0, 0);
    GU_COPY(1, 1);
    for (int kt = 0; kt < KT; kt++) {
        int cur = kt % 3;
        // wait for this tile's copies (own), then barrier => all threads' copies visible
        if (kt + 1 < KT) asm volatile("cp.async.wait_group 1;" ::: "memory");
        else             asm volatile("cp.async.wait_group 0;" ::: "memory");
        __syncthreads();
        // issue prefetch AFTER barrier: target buffer's last readers are done
        if (kt + 2 < KT) GU_COPY((kt + 2) % 3, kt + 2);
        uint32_t base = smA + cur * (3 * TILE_B);
#pragma unroll
        for (int ks = 0; ks < 2; ks++) {
            uint32_t a0[4], a1[4], bg0[4], bg1[4], bu0[4], bu1[4];
            ldsm4(a0, base + offA + ks * 32);
            ldsm4(a1, base + offA + 1280 + ks * 32);
            ldsm4(bg0, base + TILE_B + offB + ks * 32);
            ldsm4(bg1, base + TILE_B + offB + 1280 + ks * 32);
            ldsm4(bu0, base + 2 * TILE_B + offB + ks * 32);
            ldsm4(bu1, base + 2 * TILE_B + offB + 1280 + ks * 32);
#pragma unroll
            for (int mm = 0; mm < 2; mm++) {
                const uint32_t* a = mm ? a1 : a0;
                mma16(ag[mm][0], a, bg0);
                mma16(ag[mm][1], a, bg0 + 2);
                mma16(ag[mm][2], a, bg1);
                mma16(ag[mm][3], a, bg1 + 2);
                mma16(au[mm][0], a, bu0);
                mma16(au[mm][1], a, bu0 + 2);
                mma16(au[mm][2], a, bu1);
                mma16(au[mm][3], a, bu1 + 2);
            }
        }
    }

    // epilogue: h = half(silu(g)*u*w)
#pragma unroll
    for (int mm = 0; mm < 2; mm++) {
#pragma unroll
        for (int hh = 0; hh < 2; hh++) {
            int rglb = mtile * 128 + warpM + mm * 16 + gl + hh * 8;
            bool live = (!ROUTED) || (rglb < Me);
            if (!live) continue;
            float w = 1.0f;
            __half* dst;
            if (ROUTED) {
                int slot = start + rglb;
                w = g_slot_w[slot];
                dst = g_hbuf + (size_t)slot * HDIM + (size_t)ntile * 128;
            } else {
                dst = g_sh + (size_t)rglb * HSDIM + (size_t)ntile * 128;
            }
#pragma unroll
            for (int nn = 0; nn < 4; nn++) {
                int c = warpN + nn * 8 + 2 * kl;
                float gv0 = ag[mm][nn][hh * 2], gv1 = ag[mm][nn][hh * 2 + 1];
                float uv0 = au[mm][nn][hh * 2], uv1 = au[mm][nn][hh * 2 + 1];
                __half2 h2 = __floats2half2_rn(silu_f(gv0) * uv0 * w,
                                               silu_f(gv1) * uv1 * w);
                *(__half2*)(dst + c) = h2;
            }
        }
    }
}

// ---------------- down GEMM: mma.sync fp16 + ldmatrix, 3-stage ----------------
// out is pre-zeroed; BOTH variants accumulate with atomicAdd so the two down
// kernels may run concurrently on different streams.
template <bool ROUTED>
__global__ __launch_bounds__(512, 1)
void down_mma(const __half* __restrict__ Wd, float* __restrict__ Out) {
    extern __shared__ char smem[];
    constexpr int K = ROUTED ? HDIM : HSDIM;
    constexpr int KT = K / 32;
    uint32_t smA = s2u(smem);

    int tid = threadIdx.x, wid = tid >> 5, lane = tid & 31;
    int warpM = (wid >> 2) * 32, warpN = (wid & 3) * 32;
    int gl = lane >> 2, kl = lane & 3;
    int ntile = blockIdx.x, mtile = blockIdx.y;

    int start = 0, Me = T_TOKENS;
    if (ROUTED) {
        int expert = blockIdx.z;
        start = g_offsets[expert];
        Me = g_offsets[expert + 1] - start;
        if (mtile * 128 >= Me) return;
        Wd += (size_t)expert * HDIM * DIM;
    }
    const __half* Abase = (ROUTED ? g_hbuf : g_sh) + (size_t)(start + mtile * 128) * K;

    int crow = tid >> 2, seg = tid & 3;
    const __half* pA = Abase + (size_t)crow * K + seg * 8;
    const __half* pB = Wd + (size_t)(ntile * 128 + crow) * K + seg * 8;
    uint32_t dOff = smA + (crow * AST + seg * 8) * 2;

#define DN_COPY(stg, kt) do { \
    uint32_t _b = dOff + (stg) * (2 * TILE_B); \
    cp16(_b,          pA + (kt) * 32); \
    cp16(_b + TILE_B, pB + (kt) * 32); \
    cp_commit(); \
} while (0)

    int l8 = lane & 7, lj = lane >> 3;
    uint32_t offA = (uint32_t)((warpM + (lj & 1) * 8 + l8) * AST + (lj >> 1) * 8) * 2;
    uint32_t offB = (uint32_t)((warpN + (lj >> 1) * 8 + l8) * AST + (lj & 1) * 8) * 2;

    float acc[2][4][4];
#pragma unroll
    for (int mm = 0; mm < 2; mm++)
#pragma unroll
        for (int nn = 0; nn < 4; nn++)
#pragma unroll
            for (int q = 0; q < 4; q++) acc[mm][nn][q] = 0.f;

    DN_COPY(0, 0);
    DN_COPY(1, 1);
    for (int kt = 0; kt < KT; kt++) {
        int cur = kt % 3;
        if (kt + 1 < KT) asm volatile("cp.async.wait_group 1;" ::: "memory");
        else             asm volatile("cp.async.wait_group 0;" ::: "memory");
        __syncthreads();
        if (kt + 2 < KT) DN_COPY((kt + 2) % 3, kt + 2);
        uint32_t base = smA + cur * (2 * TILE_B);
#pragma unroll
        for (int ks = 0; ks < 2; ks++) {
            uint32_t a0[4], a1[4], b0[4], b1[4];
            ldsm4(a0, base + offA + ks * 32);
            ldsm4(a1, base + offA + 1280 + ks * 32);
            ldsm4(b0, base + TILE_B + offB + ks * 32);
            ldsm4(b1, base + TILE_B + offB + 1280 + ks * 32);
#pragma unroll
            for (int mm = 0; mm < 2; mm++) {
                const uint32_t* a = mm ? a1 : a0;
                mma16(acc[mm][0], a, b0);
                mma16(acc[mm][1], a, b0 + 2);
                mma16(acc[mm][2], a, b1);
                mma16(acc[mm][3], a, b1 + 2);
            }
        }
    }

#pragma unroll
    for (int mm = 0; mm < 2; mm++) {
#pragma unroll
        for (int hh = 0; hh < 2; hh++) {
            int rglb = mtile * 128 + warpM + mm * 16 + gl + hh * 8;
            bool live = (!ROUTED) || (rglb < Me);
            if (!live) continue;
            float* dst;
            if (ROUTED) {
                int token = g_slot_token[start + rglb];
                dst = Out + (size_t)token * DIM + (size_t)ntile * 128;
            } else {
                dst = Out + (size_t)rglb * DIM + (size_t)ntile * 128;
            }
#pragma unroll
            for (int nn = 0; nn < 4; nn++) {
                int c = warpN + nn * 8 + 2 * kl;
                atomicAdd(dst + c, acc[mm][nn][hh * 2]);
                atomicAdd(dst + c + 1, acc[mm][nn][hh * 2 + 1]);
            }
        }
    }
}

// ---------------- launch ----------------
extern "C" void kernel_launch(void* const* d_in, const int* in_sizes, int n_in,
                              void* d_out, int out_size) {
    const float* x   = (const float*)d_in[0];
    const float* rw  = (const float*)d_in[1];
    const float* wg  = (const float*)d_in[2];
    const float* wu  = (const float*)d_in[3];
    const float* wd  = (const float*)d_in[4];
    const float* swg = (const float*)d_in[5];
    const float* swu = (const float*)d_in[6];
    const float* swd = (const float*)d_in[7];
    float* out = (float*)d_out;

    // lazy host-object init (first call is the non-captured correctness run)
    static cudaStream_t s1 = nullptr, s2 = nullptr;
    static cudaEvent_t evFork = nullptr, evSg = nullptr, evSu = nullptr, evGU = nullptr;
    static cudaEvent_t evSD = nullptr, evWD = nullptr, evRoute = nullptr;
    static cudaEvent_t evX = nullptr, evRD = nullptr;
    if (s1 == nullptr) {
        cudaStreamCreateWithFlags(&s1, cudaStreamNonBlocking);
        cudaStreamCreateWithFlags(&s2, cudaStreamNonBlocking);
        cudaEventCreateWithFlags(&evFork, cudaEventDisableTiming);
        cudaEventCreateWithFlags(&evSg, cudaEventDisableTiming);
        cudaEventCreateWithFlags(&evSu, cudaEventDisableTiming);
        cudaEventCreateWithFlags(&evGU, cudaEventDisableTiming);
        cudaEventCreateWithFlags(&evSD, cudaEventDisableTiming);
        cudaEventCreateWithFlags(&evWD, cudaEventDisableTiming);
        cudaEventCreateWithFlags(&evRoute, cudaEventDisableTiming);
        cudaEventCreateWithFlags(&evX, cudaEventDisableTiming);
        cudaEventCreateWithFlags(&evRD, cudaEventDisableTiming);
        cudaFuncSetAttribute(gateup_mma<false>, cudaFuncAttributeMaxDynamicSharedMemorySize, GU_SMEM);
        cudaFuncSetAttribute(gateup_mma<true>,  cudaFuncAttributeMaxDynamicSharedMemorySize, GU_SMEM);
        cudaFuncSetAttribute(down_mma<false>,   cudaFuncAttributeMaxDynamicSharedMemorySize, DN_SMEM);
        cudaFuncSetAttribute(down_mma<true>,    cudaFuncAttributeMaxDynamicSharedMemorySize, DN_SMEM);
    }

    __half *wgh, *wuh, *wdh, *swgh, *swuh, *swdh;
    cudaGetSymbolAddress((void**)&wgh, g_wgh);
    cudaGetSymbolAddress((void**)&wuh, g_wuh);
    cudaGetSymbolAddress((void**)&wdh, g_wdh);
    cudaGetSymbolAddress((void**)&swgh, g_swgh);
    cudaGetSymbolAddress((void**)&swuh, g_swuh);
    cudaGetSymbolAddress((void**)&swdh, g_swdh);

    // fork
    cudaEventRecord(evFork, 0);
    cudaStreamWaitEvent(s1, evFork, 0);
    cudaStreamWaitEvent(s2, evFork, 0);

    // s1: swg first (shared-gateup gate), then routed gate/up, then down weights
    convw_t_kernel<<<dim3(HSDIM / 32, DIM / 32, 1), dim3(32, 8), 0, s1>>>(swg, swgh, DIM, HSDIM);
    cudaEventRecord(evSg, s1);
    convw_t_kernel<<<dim3(HDIM / 32, DIM / 32, NEXP), dim3(32, 8), 0, s1>>>(wg, wgh, DIM, HDIM);
    convw_t_kernel<<<dim3(HDIM / 32, DIM / 32, NEXP), dim3(32, 8), 0, s1>>>(wu, wuh, DIM, HDIM);
    cudaEventRecord(evGU, s1);
    convw_t_kernel<<<dim3(DIM / 32, HSDIM / 32, 1), dim3(32, 8), 0, s1>>>(swd, swdh, HSDIM, DIM);
    cudaEventRecord(evSD, s1);
    convw_t_kernel<<<dim3(DIM / 32, HDIM / 32, NEXP), dim3(32, 8), 0, s1>>>(wd, wdh, HDIM, DIM);
    cudaEventRecord(evWD, s1);

    // s2: swu conversion in parallel with swg, then activation conversion
    convw_t_kernel<<<dim3(HSDIM / 32, DIM / 32, 1), dim3(32, 8), 0, s2>>>(swu, swuh, DIM, HSDIM);
    cudaEventRecord(evSu, s2);
    conv_x_kernel<<<T_TOKENS, 256, 0, s2>>>(x);
    cudaEventRecord(evX, s2);

    // main: output zero + routing chain
    zero_out_kernel<<<T_TOKENS * DIM / 4 / 256, 256>>>(out);
    zero_small_kernel<<<1, 32>>>();
    router_kernel<<<T_TOKENS / 8, 256>>>(x, rw);
    scan_kernel<<<1, 32>>>();
    scatter_kernel<<<NSLOTS / 256, 256>>>();
    cudaEventRecord(evRoute, 0);

    // s2: routed chain (gateup then down), concurrent with shared chain on main
    cudaStreamWaitEvent(s2, evRoute, 0);
    cudaStreamWaitEvent(s2, evGU, 0);
    gateup_mma<true><<<dim3(HDIM / 128, NSLOTS / 128, NEXP), 512, GU_SMEM, s2>>>(wgh, wuh);
    cudaStreamWaitEvent(s2, evWD, 0);
    down_mma<true><<<dim3(DIM / 128, NSLOTS / 128, NEXP), 512, DN_SMEM, s2>>>(wdh, out);
    cudaEventRecord(evRD, s2);

    // main: shared chain (gateup then down), then join
    cudaStreamWaitEvent(0, evSg, 0);
    cudaStreamWaitEvent(0, evSu, 0);
    cudaStreamWaitEvent(0, evX, 0);
    gateup_mma<false><<<dim3(HSDIM / 128, T_TOKENS / 128, 1), 512, GU_SMEM>>>(swgh, swuh);
    cudaStreamWaitEvent(0, evSD, 0);
    down_mma<false><<<dim3(DIM / 128, T_TOKENS / 128, 1), 512, DN_SMEM>>>(swdh, out);
    cudaStreamWaitEvent(0, evRD, 0);
    join_kernel<<<1, 1>>>();
}

// round 17
// speedup vs baseline: 1.0195x; 1.0195x over previous
#include <cuda_runtime.h>
#include <cuda_fp16.h>
#include <cstdint>

#define T_TOKENS 4096
#define DIM      2048
#define NEXP     8
#define HDIM     1024
#define HSDIM    2048
#define NSLOTS   8192
#define PAD      128

// ---------------- scratch (device globals; no allocation allowed) ----------------
__device__ __half g_xr[(size_t)T_TOKENS * DIM];          // fp16 dense x
__device__ __half g_hbuf[(size_t)(NSLOTS + PAD) * HDIM]; // routed h (weight-folded)
__device__ __half g_sh[(size_t)T_TOKENS * HSDIM];        // shared-expert h
__device__ __half g_wgh[(size_t)NEXP * DIM * HDIM];      // transposed [e][n=h][k=d] fp16
__device__ __half g_wuh[(size_t)NEXP * DIM * HDIM];
__device__ __half g_wdh[(size_t)NEXP * HDIM * DIM];      // [e][n=d][k=h]
__device__ __half g_swgh[(size_t)DIM * HSDIM];           // [n=hs][k=d]
__device__ __half g_swuh[(size_t)DIM * HSDIM];
__device__ __half g_swdh[(size_t)HSDIM * DIM];           // [n=d][k=hs]
__device__ int   g_slot_token[NSLOTS];
__device__ float g_slot_w[NSLOTS];
__device__ int   g_counts[NEXP];
__device__ int   g_fill[NEXP];
__device__ int   g_offsets[NEXP + 1];
__device__ int   g_eidx[NSLOTS];
__device__ float g_topw[NSLOTS];

// ---------------- helpers ----------------
__device__ __forceinline__ float silu_f(float g) {
    return g * (1.0f / (1.0f + __expf(-g)));
}
__device__ __forceinline__ uint32_t s2u(const void* p) {
    uint32_t a;
    asm("{ .reg .u64 t; cvta.to.shared.u64 t, %1; cvt.u32.u64 %0, t; }" : "=r"(a) : "l"(p));
    return a;
}
__device__ __forceinline__ void cp16(uint32_t s, const void* g) {
    asm volatile("cp.async.cg.shared.global [%0], [%1], 16;" :: "r"(s), "l"(g));
}
__device__ __forceinline__ void cp_commit() {
    asm volatile("cp.async.commit_group;" ::: "memory");
}
__device__ __forceinline__ void mma16(float* c, const uint32_t* a, const uint32_t* b) {
    asm volatile("mma.sync.aligned.m16n8k16.row.col.f32.f16.f16.f32 "
        "{%0,%1,%2,%3}, {%4,%5,%6,%7}, {%8,%9}, {%0,%1,%2,%3};"
        : "+f"(c[0]), "+f"(c[1]), "+f"(c[2]), "+f"(c[3])
        : "r"(a[0]), "r"(a[1]), "r"(a[2]), "r"(a[3]), "r"(b[0]), "r"(b[1]));
}
__device__ __forceinline__ void ldsm4(uint32_t* d, uint32_t addr) {
    asm volatile("ldmatrix.sync.aligned.m8n8.x4.shared.b16 {%0,%1,%2,%3}, [%4];"
        : "=r"(d[0]), "=r"(d[1]), "=r"(d[2]), "=r"(d[3]) : "r"(addr));
}

// SMEM geometry: every tile (A or B) = 128 rows x 40 halves (32 data + 8 pad)
#define AST 40
#define TILE_B 10240                       // bytes per tile
#define GU_SMEM (3 * 3 * TILE_B)           // 92160 (3 stages x {A,Bg,Bu})
#define DN_SMEM (3 * 2 * TILE_B)           // 61440 (3 stages x {A,B})

// ---------------- routing kernels ----------------
__global__ void zero_small_kernel() {
    int i = threadIdx.x;
    if (i < NEXP) { g_counts[i] = 0; g_fill[i] = 0; }
}

__global__ void router_kernel(const float* __restrict__ x, const float* __restrict__ rw) {
    int t = (blockIdx.x * blockDim.x + threadIdx.x) >> 5;
    int lane = threadIdx.x & 31;
    if (t >= T_TOKENS) return;
    const float* xr = x + (size_t)t * DIM;
    float lg[NEXP];
#pragma unroll
    for (int e = 0; e < NEXP; e++) lg[e] = 0.f;
    for (int d = lane; d < DIM; d += 32) {
        float xv = xr[d];
        const float* r = rw + (size_t)d * NEXP;
#pragma unroll
        for (int e = 0; e < NEXP; e++) lg[e] += xv * r[e];
    }
#pragma unroll
    for (int e = 0; e < NEXP; e++) {
#pragma unroll
        for (int o = 16; o; o >>= 1) lg[e] += __shfl_xor_sync(0xffffffffu, lg[e], o);
    }
    if (lane == 0) {
        float mx = lg[0];
#pragma unroll
        for (int e = 1; e < NEXP; e++) mx = fmaxf(mx, lg[e]);
        float p[NEXP];
#pragma unroll
        for (int e = 0; e < NEXP; e++) p[e] = __expf(lg[e] - mx);
        int i1 = 0;
#pragma unroll
        for (int e = 1; e < NEXP; e++) if (p[e] > p[i1]) i1 = e;
        int i2 = (i1 == 0) ? 1 : 0;
#pragma unroll
        for (int e = 0; e < NEXP; e++) if (e != i1 && p[e] > p[i2]) i2 = e;
        float w1 = p[i1], w2 = p[i2];
        float s = w1 + w2;
        w1 /= s; w2 /= s;
        g_eidx[2 * t] = i1; g_eidx[2 * t + 1] = i2;
        g_topw[2 * t] = w1; g_topw[2 * t + 1] = w2;
        atomicAdd(&g_counts[i1], 1);
        atomicAdd(&g_counts[i2], 1);
    }
}

__global__ void scan_kernel() {
    if (threadIdx.x == 0) {
        int acc = 0;
        for (int e = 0; e < NEXP; e++) { g_offsets[e] = acc; acc += g_counts[e]; }
        g_offsets[NEXP] = acc;
    }
}

__global__ void scatter_kernel() {
    int i = blockIdx.x * blockDim.x + threadIdx.x;
    if (i >= NSLOTS) return;
    int e = g_eidx[i];
    int pos = g_offsets[e] + atomicAdd(&g_fill[e], 1);
    g_slot_token[pos] = i >> 1;
    g_slot_w[pos] = g_topw[i];
}

// ---------------- weight fp32 [K][N] -> fp16 transposed [N][K] ----------------
__global__ void convw_t_kernel(const float* __restrict__ src, __half* __restrict__ dst,
                               int K, int N) {
    __shared__ float t[32][33];
    size_t boff = (size_t)blockIdx.z * K * N;
    const float* ip = src + boff;
    __half* op = dst + boff;
    int c0 = blockIdx.x * 32;  // N dim
    int r0 = blockIdx.y * 32;  // K dim
    int x = threadIdx.x, y = threadIdx.y;
#pragma unroll
    for (int i = 0; i < 32; i += 8)
        t[y + i][x] = ip[(size_t)(r0 + y + i) * N + (c0 + x)];
    __syncthreads();
    int tid = y * 32 + x;
#pragma unroll
    for (int q = 0; q < 2; q++) {
        int p = tid * 2 + q;
        int nl = p >> 4, kc = p & 15;
        __half2 h2 = __floats2half2_rn(t[2 * kc][nl], t[2 * kc + 1][nl]);
        *(__half2*)(op + (size_t)(c0 + nl) * K + r0 + 2 * kc) = h2;
    }
}

// dense fp32 -> fp16 activation conversion
__global__ void conv_x_kernel(const float* __restrict__ x) {
    int r = blockIdx.x;
    int c0 = threadIdx.x * 8;
    const float* src = x + (size_t)r * DIM;
    float4 v0 = *(const float4*)(src + c0);
    float4 v1 = *(const float4*)(src + c0 + 4);
    __half h[8];
    h[0] = __float2half(v0.x); h[1] = __float2half(v0.y);
    h[2] = __float2half(v0.z); h[3] = __float2half(v0.w);
    h[4] = __float2half(v1.x); h[5] = __float2half(v1.y);
    h[6] = __float2half(v1.z); h[7] = __float2half(v1.w);
    *(uint4*)(g_xr + (size_t)r * DIM + c0) = *(uint4*)h;
}

// ---------------- fused gate/up GEMM: mma.sync fp16 + ldmatrix, 3-stage ----------------
// Block 128x128, BK=32, 512 threads (16 warps 4x4), warp tile 32x32.
// ROUTED: A rows gathered inline from g_xr via g_slot_token.
template <bool ROUTED>
__global__ __launch_bounds__(512, 1)
void gateup_mma(const __half* __restrict__ Wg, const __half* __restrict__ Wu) {
    extern __shared__ char smem[];
    constexpr int KT = DIM / 32;  // 64
    uint32_t smA = s2u(smem);

    int tid = threadIdx.x, wid = tid >> 5, lane = tid & 31;
    int warpM = (wid >> 2) * 32, warpN = (wid & 3) * 32;
    int gl = lane >> 2, kl = lane & 3;
    int ntile = blockIdx.x, mtile = blockIdx.y;

    int start = 0, Me = T_TOKENS;
    if (ROUTED) {
        int expert = blockIdx.z;
        start = g_offsets[expert];
        Me = g_offsets[expert + 1] - start;
        if (mtile * 128 >= Me) return;
        Wg += (size_t)expert * DIM * HDIM;
        Wu += (size_t)expert * DIM * HDIM;
    }

    // cp.async lanes: row = tid/4 (0..127), seg = tid%4 (16B each)
    int crow = tid >> 2, seg = tid & 3;
    const __half* pA;
    if (ROUTED) {
        int rr = mtile * 128 + crow;
        if (rr >= Me) rr = Me - 1;                     // clamp; epilogue masks
        pA = g_xr + (size_t)g_slot_token[start + rr] * DIM + seg * 8;
    } else {
        pA = g_xr + (size_t)(mtile * 128 + crow) * DIM + seg * 8;
    }
    const __half* pG = Wg + (size_t)(ntile * 128 + crow) * DIM + seg * 8;
    const __half* pU = Wu + (size_t)(ntile * 128 + crow) * DIM + seg * 8;
    uint32_t dOff = smA + (crow * AST + seg * 8) * 2;

#define GU_COPY(stg, kt) do { \
    uint32_t _b = dOff + (stg) * (3 * TILE_B); \
    cp16(_b,              pA + (kt) * 32); \
    cp16(_b + TILE_B,     pG + (kt) * 32); \
    cp16(_b + 2 * TILE_B, pU + (kt) * 32); \
    cp_commit(); \
} while (0)

    // ldmatrix lane offsets (bytes within a tile)
    int l8 = lane & 7, lj = lane >> 3;
    uint32_t offA = (uint32_t)((warpM + (lj & 1) * 8 + l8) * AST + (lj >> 1) * 8) * 2;
    uint32_t offB = (uint32_t)((warpN + (lj >> 1) * 8 + l8) * AST + (lj & 1) * 8) * 2;

    float ag[2][4][4], au[2][4][4];
#pragma unroll
    for (int mm = 0; mm < 2; mm++)
#pragma unroll
        for (int nn = 0; nn < 4; nn++)
#pragma unroll
            for (int q = 0; q < 4; q++) { ag[mm][nn][q] = 0.f; au[mm][nn][q] = 0.f; }

    GU_COPY(0, 0);
    GU_COPY(1, 1);
    for (int kt = 0; kt < KT; kt++) {
        int cur = kt % 3;
        // wait for this tile's copies (own), then barrier => all threads' copies visible
        if (kt + 1 < KT) asm volatile("cp.async.wait_group 1;" ::: "memory");
        else             asm volatile("cp.async.wait_group 0;" ::: "memory");
        __syncthreads();
        // issue prefetch AFTER barrier: target buffer's last readers are done
        if (kt + 2 < KT) GU_COPY((kt + 2) % 3, kt + 2);
        uint32_t base = smA + cur * (3 * TILE_B);
#pragma unroll
        for (int ks = 0; ks < 2; ks++) {
            uint32_t a0[4], a1[4], bg0[4], bg1[4], bu0[4], bu1[4];
            ldsm4(a0, base + offA + ks * 32);
            ldsm4(a1, base + offA + 1280 + ks * 32);
            ldsm4(bg0, base + TILE_B + offB + ks * 32);
            ldsm4(bg1, base + TILE_B + offB + 1280 + ks * 32);
            ldsm4(bu0, base + 2 * TILE_B + offB + ks * 32);
            ldsm4(bu1, base + 2 * TILE_B + offB + 1280 + ks * 32);
#pragma unroll
            for (int mm = 0; mm < 2; mm++) {
                const uint32_t* a = mm ? a1 : a0;
                mma16(ag[mm][0], a, bg0);
                mma16(ag[mm][1], a, bg0 + 2);
                mma16(ag[mm][2], a, bg1);
                mma16(ag[mm][3], a, bg1 + 2);
                mma16(au[mm][0], a, bu0);
                mma16(au[mm][1], a, bu0 + 2);
                mma16(au[mm][2], a, bu1);
                mma16(au[mm][3], a, bu1 + 2);
            }
        }
    }

    // epilogue: h = half(silu(g)*u*w)
#pragma unroll
    for (int mm = 0; mm < 2; mm++) {
#pragma unroll
        for (int hh = 0; hh < 2; hh++) {
            int rglb = mtile * 128 + warpM + mm * 16 + gl + hh * 8;
            bool live = (!ROUTED) || (rglb < Me);
            if (!live) continue;
            float w = 1.0f;
            __half* dst;
            if (ROUTED) {
                int slot = start + rglb;
                w = g_slot_w[slot];
                dst = g_hbuf + (size_t)slot * HDIM + (size_t)ntile * 128;
            } else {
                dst = g_sh + (size_t)rglb * HSDIM + (size_t)ntile * 128;
            }
#pragma unroll
            for (int nn = 0; nn < 4; nn++) {
                int c = warpN + nn * 8 + 2 * kl;
                float gv0 = ag[mm][nn][hh * 2], gv1 = ag[mm][nn][hh * 2 + 1];
                float uv0 = au[mm][nn][hh * 2], uv1 = au[mm][nn][hh * 2 + 1];
                __half2 h2 = __floats2half2_rn(silu_f(gv0) * uv0 * w,
                                               silu_f(gv1) * uv1 * w);
                *(__half2*)(dst + c) = h2;
            }
        }
    }
}

// ---------------- down GEMM: mma.sync fp16 + ldmatrix, 3-stage ----------------
// ROUTED: atomicAdd into out (after shared-down initialized it with plain stores).
template <bool ROUTED>
__global__ __launch_bounds__(512, 1)
void down_mma(const __half* __restrict__ Wd, float* __restrict__ Out) {
    extern __shared__ char smem[];
    constexpr int K = ROUTED ? HDIM : HSDIM;
    constexpr int KT = K / 32;
    uint32_t smA = s2u(smem);

    int tid = threadIdx.x, wid = tid >> 5, lane = tid & 31;
    int warpM = (wid >> 2) * 32, warpN = (wid & 3) * 32;
    int gl = lane >> 2, kl = lane & 3;
    int ntile = blockIdx.x, mtile = blockIdx.y;

    int start = 0, Me = T_TOKENS;
    if (ROUTED) {
        int expert = blockIdx.z;
        start = g_offsets[expert];
        Me = g_offsets[expert + 1] - start;
        if (mtile * 128 >= Me) return;
        Wd += (size_t)expert * HDIM * DIM;
    }
    const __half* Abase = (ROUTED ? g_hbuf : g_sh) + (size_t)(start + mtile * 128) * K;

    int crow = tid >> 2, seg = tid & 3;
    const __half* pA = Abase + (size_t)crow * K + seg * 8;
    const __half* pB = Wd + (size_t)(ntile * 128 + crow) * K + seg * 8;
    uint32_t dOff = smA + (crow * AST + seg * 8) * 2;

#define DN_COPY(stg, kt) do { \
    uint32_t _b = dOff + (stg) * (2 * TILE_B); \
    cp16(_b,          pA + (kt) * 32); \
    cp16(_b + TILE_B, pB + (kt) * 32); \
    cp_commit(); \
} while (0)

    int l8 = lane & 7, lj = lane >> 3;
    uint32_t offA = (uint32_t)((warpM + (lj & 1) * 8 + l8) * AST + (lj >> 1) * 8) * 2;
    uint32_t offB = (uint32_t)((warpN + (lj >> 1) * 8 + l8) * AST + (lj & 1) * 8) * 2;

    float acc[2][4][4];
#pragma unroll
    for (int mm = 0; mm < 2; mm++)
#pragma unroll
        for (int nn = 0; nn < 4; nn++)
#pragma unroll
            for (int q = 0; q < 4; q++) acc[mm][nn][q] = 0.f;

    DN_COPY(0, 0);
    DN_COPY(1, 1);
    for (int kt = 0; kt < KT; kt++) {
        int cur = kt % 3;
        if (kt + 1 < KT) asm volatile("cp.async.wait_group 1;" ::: "memory");
        else             asm volatile("cp.async.wait_group 0;" ::: "memory");
        __syncthreads();
        if (kt + 2 < KT) DN_COPY((kt + 2) % 3, kt + 2);
        uint32_t base = smA + cur * (2 * TILE_B);
#pragma unroll
        for (int ks = 0; ks < 2; ks++) {
            uint32_t a0[4], a1[4], b0[4], b1[4];
            ldsm4(a0, base + offA + ks * 32);
            ldsm4(a1, base + offA + 1280 + ks * 32);
            ldsm4(b0, base + TILE_B + offB + ks * 32);
            ldsm4(b1, base + TILE_B + offB + 1280 + ks * 32);
#pragma unroll
            for (int mm = 0; mm < 2; mm++) {
                const uint32_t* a = mm ? a1 : a0;
                mma16(acc[mm][0], a, b0);
                mma16(acc[mm][1], a, b0 + 2);
                mma16(acc[mm][2], a, b1);
                mma16(acc[mm][3], a, b1 + 2);
            }
        }
    }

#pragma unroll
    for (int mm = 0; mm < 2; mm++) {
#pragma unroll
        for (int hh = 0; hh < 2; hh++) {
            int rglb = mtile * 128 + warpM + mm * 16 + gl + hh * 8;
            bool live = (!ROUTED) || (rglb < Me);
            if (!live) continue;
            float* dst;
            if (ROUTED) {
                int token = g_slot_token[start + rglb];
                dst = Out + (size_t)token * DIM + (size_t)ntile * 128;
            } else {
                dst = Out + (size_t)rglb * DIM + (size_t)ntile * 128;
            }
#pragma unroll
            for (int nn = 0; nn < 4; nn++) {
                int c = warpN + nn * 8 + 2 * kl;
                float v0 = acc[mm][nn][hh * 2], v1 = acc[mm][nn][hh * 2 + 1];
                if (ROUTED) {
                    atomicAdd(dst + c, v0);
                    atomicAdd(dst + c + 1, v1);
                } else {
                    float2 v; v.x = v0; v.y = v1;
                    *(float2*)(dst + c) = v;
                }
            }
        }
    }
}

// ---------------- launch ----------------
extern "C" void kernel_launch(void* const* d_in, const int* in_sizes, int n_in,
                              void* d_out, int out_size) {
    const float* x   = (const float*)d_in[0];
    const float* rw  = (const float*)d_in[1];
    const float* wg  = (const float*)d_in[2];
    const float* wu  = (const float*)d_in[3];
    const float* wd  = (const float*)d_in[4];
    const float* swg = (const float*)d_in[5];
    const float* swu = (const float*)d_in[6];
    const float* swd = (const float*)d_in[7];
    float* out = (float*)d_out;

    // lazy host-object init (first call is the non-captured correctness run)
    static cudaStream_t s1 = nullptr, s2 = nullptr;
    static cudaEvent_t evFork = nullptr, evSg = nullptr, evSu = nullptr, evGU = nullptr;
    static cudaEvent_t evSD = nullptr, evWD = nullptr, evRoute = nullptr;
    static cudaEvent_t evX = nullptr, evRG = nullptr;
    if (s1 == nullptr) {
        cudaStreamCreateWithFlags(&s1, cudaStreamNonBlocking);
        cudaStreamCreateWithFlags(&s2, cudaStreamNonBlocking);
        cudaEventCreateWithFlags(&evFork, cudaEventDisableTiming);
        cudaEventCreateWithFlags(&evSg, cudaEventDisableTiming);
        cudaEventCreateWithFlags(&evSu, cudaEventDisableTiming);
        cudaEventCreateWithFlags(&evGU, cudaEventDisableTiming);
        cudaEventCreateWithFlags(&evSD, cudaEventDisableTiming);
        cudaEventCreateWithFlags(&evWD, cudaEventDisableTiming);
        cudaEventCreateWithFlags(&evRoute, cudaEventDisableTiming);
        cudaEventCreateWithFlags(&evX, cudaEventDisableTiming);
        cudaEventCreateWithFlags(&evRG, cudaEventDisableTiming);
        cudaFuncSetAttribute(gateup_mma<false>, cudaFuncAttributeMaxDynamicSharedMemorySize, GU_SMEM);
        cudaFuncSetAttribute(gateup_mma<true>,  cudaFuncAttributeMaxDynamicSharedMemorySize, GU_SMEM);
        cudaFuncSetAttribute(down_mma<false>,   cudaFuncAttributeMaxDynamicSharedMemorySize, DN_SMEM);
        cudaFuncSetAttribute(down_mma<true>,    cudaFuncAttributeMaxDynamicSharedMemorySize, DN_SMEM);
    }

    __half *wgh, *wuh, *wdh, *swgh, *swuh, *swdh;
    cudaGetSymbolAddress((void**)&wgh, g_wgh);
    cudaGetSymbolAddress((void**)&wuh, g_wuh);
    cudaGetSymbolAddress((void**)&wdh, g_wdh);
    cudaGetSymbolAddress((void**)&swgh, g_swgh);
    cudaGetSymbolAddress((void**)&swuh, g_swuh);
    cudaGetSymbolAddress((void**)&swdh, g_swdh);

    // fork
    cudaEventRecord(evFork, 0);
    cudaStreamWaitEvent(s1, evFork, 0);
    cudaStreamWaitEvent(s2, evFork, 0);

    // s1: swg, then routed gate/up weights, then down weights
    convw_t_kernel<<<dim3(HSDIM / 32, DIM / 32, 1), dim3(32, 8), 0, s1>>>(swg, swgh, DIM, HSDIM);
    cudaEventRecord(evSg, s1);
    convw_t_kernel<<<dim3(HDIM / 32, DIM / 32, NEXP), dim3(32, 8), 0, s1>>>(wg, wgh, DIM, HDIM);
    convw_t_kernel<<<dim3(HDIM / 32, DIM / 32, NEXP), dim3(32, 8), 0, s1>>>(wu, wuh, DIM, HDIM);
    cudaEventRecord(evGU, s1);
    convw_t_kernel<<<dim3(DIM / 32, HSDIM / 32, 1), dim3(32, 8), 0, s1>>>(swd, swdh, HSDIM, DIM);
    cudaEventRecord(evSD, s1);
    convw_t_kernel<<<dim3(DIM / 32, HDIM / 32, NEXP), dim3(32, 8), 0, s1>>>(wd, wdh, HDIM, DIM);
    cudaEventRecord(evWD, s1);

    // s2: swu conversion (parallel with swg), then activation conversion
    convw_t_kernel<<<dim3(HSDIM / 32, DIM / 32, 1), dim3(32, 8), 0, s2>>>(swu, swuh, DIM, HSDIM);
    cudaEventRecord(evSu, s2);
    conv_x_kernel<<<T_TOKENS, 256, 0, s2>>>(x);
    cudaEventRecord(evX, s2);

    // main: routing chain
    zero_small_kernel<<<1, 32>>>();
    router_kernel<<<T_TOKENS / 8, 256>>>(x, rw);
    scan_kernel<<<1, 32>>>();
    scatter_kernel<<<NSLOTS / 256, 256>>>();
    cudaEventRecord(evRoute, 0);

    // s2: routed gate/up, overlapping the shared chain on main
    cudaStreamWaitEvent(s2, evRoute, 0);
    cudaStreamWaitEvent(s2, evGU, 0);
    gateup_mma<true><<<dim3(HDIM / 128, NSLOTS / 128, NEXP), 512, GU_SMEM, s2>>>(wgh, wuh);
    cudaEventRecord(evRG, s2);

    // main: shared chain, then routed down (after shared-down's init stores + evRG)
    cudaStreamWaitEvent(0, evSg, 0);
    cudaStreamWaitEvent(0, evSu, 0);
    cudaStreamWaitEvent(0, evX, 0);
    gateup_mma<false><<<dim3(HSDIM / 128, T_TOKENS / 128, 1), 512, GU_SMEM>>>(swgh, swuh);
    cudaStreamWaitEvent(0, evSD, 0);
    down_mma<false><<<dim3(DIM / 128, T_TOKENS / 128, 1), 512, DN_SMEM>>>(swdh, out);
    cudaStreamWaitEvent(0, evRG, 0);
    cudaStreamWaitEvent(0, evWD, 0);
    down_mma<true><<<dim3(DIM / 128, NSLOTS / 128, NEXP), 512, DN_SMEM>>>(wdh, out);
}